// round 13
// baseline (speedup 1.0000x reference)
#include <cuda_runtime.h>
#include <cuda_fp16.h>
#include <cstdint>

// ---------------------------------------------------------------------------
// CombinedHiddenEncoder — R12: launch-count reduction (12 -> 10: zero+prep
// merged; scan3 folded into scan1/scan2/consumers) + agg edge-loop unroll x2.
//
//   setup1: zero cnt, dtype-detect, fold weights (g_UT, bq, WcatTH, bcat)
//   count_deg -> scan1 (exclusive-partial offsets, re-zero cnt, dinv)
//   -> scan2 (block prefix bpre, patch g_off[NN]) -> scatter
//   P = [F|C]@UT^T (HMMA) ; Q = A·P + bq ; R = A·Q + b3 ; G = A·R
//   (mean|lv) = G@WcatTH^T + bcat; z fused in epilogue (HMMA)
//
// Offsets at use: start = g_off[i] + g_bpre[i>>8]; end likewise for i+1.
// d_out (O = float[9.6M]): P=[0:3.2M) Q=[3.2M:6.4M) R=[6.4M:9.6M) fp16;
//   G over dead P; z over own G rows; mean over dead Q; lv over dead R.
// ---------------------------------------------------------------------------

#define NN 50000
#define NE 600000
#define NB_SCAN 196

// ------------------------- device statics (~2 MB) --------------------------
__device__ unsigned short g_src[NE];
__device__ int    g_cnt[NN];
__device__ int    g_off[NN + 1];          // partial-exclusive (add g_bpre)
__device__ float  g_dinv[NN];
__device__ int    g_bsum[256];
__device__ int    g_bpre[256];
__device__ __half g_UT[128 * 384];        // [n][k], k<256 from U1, rest U2
__device__ float  g_bq[128];
__device__ __half g_WcatTH[128 * 128];    // [n][k], n interleaved (e=Wm,o=Wv)
__device__ float  g_bcat[128];            // interleaved [bm|bv]
__device__ int    g_is64;

// ------------------------- mma helpers -------------------------------------
__device__ __forceinline__ uint32_t s2u(const void* p) {
    return (uint32_t)__cvta_generic_to_shared(p);
}
__device__ __forceinline__ void ldsm_x4(uint32_t addr, uint32_t& r0, uint32_t& r1,
                                        uint32_t& r2, uint32_t& r3) {
    asm volatile("ldmatrix.sync.aligned.m8n8.x4.shared.b16 {%0,%1,%2,%3}, [%4];"
                 : "=r"(r0), "=r"(r1), "=r"(r2), "=r"(r3) : "r"(addr));
}
__device__ __forceinline__ void mma16816(float* c, const uint32_t* a,
                                         uint32_t b0, uint32_t b1) {
    asm volatile(
        "mma.sync.aligned.m16n8k16.row.col.f32.f16.f16.f32 "
        "{%0,%1,%2,%3}, {%4,%5,%6,%7}, {%8,%9}, {%0,%1,%2,%3};"
        : "+f"(c[0]), "+f"(c[1]), "+f"(c[2]), "+f"(c[3])
        : "r"(a[0]), "r"(a[1]), "r"(a[2]), "r"(a[3]), "r"(b0), "r"(b1));
}

// ------------------------- setup1: zero + detect + weight folding ----------
__global__ void setup1_kernel(const int* __restrict__ ei32,
                              const float* __restrict__ W1, const float* __restrict__ W2,
                              const float* __restrict__ W3, const float* __restrict__ b1,
                              const float* __restrict__ b2,
                              const float* __restrict__ Wm, const float* __restrict__ Wv,
                              const float* __restrict__ bm, const float* __restrict__ bv) {
    int idx = blockIdx.x * blockDim.x + threadIdx.x;
    if (idx < NN) g_cnt[idx] = 0;
    if (blockIdx.x == 0 && threadIdx.x < 32) {   // int64 detect (warp)
        int nz = 0;
        for (int k = 0; k < 16; k++) nz |= ei32[2 * (threadIdx.x * 16 + k) + 1];
        nz = __reduce_or_sync(0xffffffffu, nz);
        if (threadIdx.x == 0) g_is64 = (nz == 0) ? 1 : 0;
    }
    if (idx < 49152) {                             // g_UT[n][k]
        int n = idx / 384, k = idx % 384;
        float a = 0.f;
        if (k < 256) {
            for (int j = 0; j < 128; j++) a += W1[k * 128 + j] * W3[j * 128 + n];
        } else {
            int kc = k - 256;
            for (int j = 0; j < 128; j++) a += W2[kc * 128 + j] * W3[(128 + j) * 128 + n];
        }
        g_UT[n * 384 + k] = __float2half_rn(a);
    } else if (idx < 49280) {                      // bq
        int n = idx - 49152;
        float a = 0.f;
        for (int j = 0; j < 128; j++)
            a += b1[j] * W3[j * 128 + n] + b2[j] * W3[(128 + j) * 128 + n];
        g_bq[n] = a;
    } else if (idx < 65664) {                      // g_WcatTH[n][k]
        int t = idx - 49280;
        int n = t >> 7, k = t & 127;
        float v = (n & 1) ? Wv[k * 64 + (n >> 1)] : Wm[k * 64 + (n >> 1)];
        g_WcatTH[n * 128 + k] = __float2half_rn(v);
    } else if (idx < 65792) {                      // bcat interleaved
        int n = idx - 65664;
        g_bcat[n] = (n & 1) ? bv[n >> 1] : bm[n >> 1];
    }
}

__device__ __forceinline__ int edge_val(const void* ei, int idx) {
    if (g_is64) return (int)((const long long*)ei)[idx];
    return ((const int*)ei)[idx];
}

__global__ void count_deg_kernel(const void* __restrict__ ei) {
    int e = blockIdx.x * blockDim.x + threadIdx.x;
    if (e >= NE) return;
    atomicAdd(&g_cnt[edge_val(ei, NE + e)], 1);
}

// Partial-exclusive scan per block; also dinv; re-zeroes cnt for scatter.
__global__ void scan1_kernel() {
    __shared__ int s[256];
    int tid = threadIdx.x;
    int i = blockIdx.x * 256 + tid;
    int v = (i < NN) ? g_cnt[i] : 0;
    if (i < NN) { g_dinv[i] = rsqrtf((float)(v + 1)); g_cnt[i] = 0; }
    s[tid] = v;
    __syncthreads();
    for (int off = 1; off < 256; off <<= 1) {
        int t = (tid >= off) ? s[tid - off] : 0;
        __syncthreads();
        s[tid] += t;
        __syncthreads();
    }
    if (i < NN) g_off[i] = s[tid] - v;   // block-local exclusive
    if (tid == 255) g_bsum[blockIdx.x] = s[255];
}

// Block prefix; thread 195 patches g_off[NN] so end(NN-1) resolves to NE.
__global__ void scan2_kernel() {
    __shared__ int s[256];
    int tid = threadIdx.x;
    int v = (tid < NB_SCAN) ? g_bsum[tid] : 0;
    s[tid] = v;
    __syncthreads();
    for (int off = 1; off < 256; off <<= 1) {
        int t = (tid >= off) ? s[tid - off] : 0;
        __syncthreads();
        s[tid] += t;
        __syncthreads();
    }
    int bpre = s[tid] - v;
    g_bpre[tid] = bpre;
    if (tid == (NN >> 8)) g_off[NN] = NE - bpre;   // 50000>>8 = 195
}

__global__ void scatter_kernel(const void* __restrict__ ei) {
    int e = blockIdx.x * blockDim.x + threadIdx.x;
    if (e >= NE) return;
    int s = edge_val(ei, e);
    int d = edge_val(ei, NE + e);
    int p = g_off[d] + g_bpre[d >> 8] + atomicAdd(&g_cnt[d], 1);
    g_src[p] = (unsigned short)s;
}

// ------------------------- GEMM-P (HMMA): P(fp16) = [F|C]@UT^T -------------
__global__ __launch_bounds__(256) void gemmP_kernel(
    const float* __restrict__ F, const float* __restrict__ C,
    __half* __restrict__ P)
{
    __shared__ __align__(16) __half As[128 * 72];
    __shared__ __align__(16) __half Bs[128 * 72];
    int tid = threadIdx.x, lane = tid & 31, wid = tid >> 5;
    int wm = (wid & 3) * 32, wn = (wid >> 2) * 64;
    int rowBase = blockIdx.x * 128;
    float c[2][8][4];
#pragma unroll
    for (int mt = 0; mt < 2; mt++)
#pragma unroll
        for (int j = 0; j < 8; j++)
#pragma unroll
            for (int q = 0; q < 4; q++) c[mt][j][q] = 0.f;

    for (int s = 0; s < 6; s++) {
        const float* A = (s < 4) ? F : C;
        int ldA = (s < 4) ? 256 : 128;
        int kb  = (s < 4) ? s * 64 : (s - 4) * 64;   // A-local k offset
        int kbB = s * 64;                             // GLOBAL k offset into UT
#pragma unroll
        for (int l = 0; l < 8; l++) {
            int fid = tid + l * 256;
            int r = fid >> 4, c4 = fid & 15;
            int gr = rowBase + r;
            float4 v = make_float4(0.f, 0.f, 0.f, 0.f);
            if (gr < NN) v = *(const float4*)&A[(size_t)gr * ldA + kb + c4 * 4];
            __half2 h0 = __floats2half2_rn(v.x, v.y);
            __half2 h1 = __floats2half2_rn(v.z, v.w);
            uint2 u = make_uint2(*(uint32_t*)&h0, *(uint32_t*)&h1);
            *(uint2*)&As[r * 72 + c4 * 4] = u;
        }
#pragma unroll
        for (int l = 0; l < 4; l++) {
            int hid = tid + l * 256;
            int n = hid >> 3, c8 = hid & 7;
            *(uint4*)&Bs[n * 72 + c8 * 8] = *(const uint4*)&g_UT[n * 384 + kbB + c8 * 8];
        }
        __syncthreads();
#pragma unroll
        for (int kk = 0; kk < 4; kk++) {
            uint32_t a[2][4], b[4][4];
#pragma unroll
            for (int mt = 0; mt < 2; mt++) {
                int row = wm + mt * 16 + (lane & 7) + 8 * ((lane >> 3) & 1);
                int col = kk * 16 + 8 * (lane >> 4);
                ldsm_x4(s2u(&As[row * 72 + col]), a[mt][0], a[mt][1], a[mt][2], a[mt][3]);
            }
#pragma unroll
            for (int jp = 0; jp < 4; jp++) {
                int row = wn + jp * 16 + (lane & 7) + 8 * (lane >> 4);
                int col = kk * 16 + 8 * ((lane >> 3) & 1);
                ldsm_x4(s2u(&Bs[row * 72 + col]), b[jp][0], b[jp][1], b[jp][2], b[jp][3]);
            }
#pragma unroll
            for (int mt = 0; mt < 2; mt++)
#pragma unroll
                for (int jp = 0; jp < 4; jp++) {
                    mma16816(c[mt][jp * 2],     a[mt], b[jp][0], b[jp][1]);
                    mma16816(c[mt][jp * 2 + 1], a[mt], b[jp][2], b[jp][3]);
                }
        }
        __syncthreads();
    }
#pragma unroll
    for (int mt = 0; mt < 2; mt++)
#pragma unroll
        for (int j = 0; j < 8; j++) {
            int r0 = rowBase + wm + mt * 16 + (lane >> 2);
            int n  = wn + j * 8 + 2 * (lane & 3);
            if (r0 < NN)
                *(__half2*)&P[(size_t)r0 * 128 + n] =
                    __floats2half2_rn(c[mt][j][0], c[mt][j][1]);
            int r1 = r0 + 8;
            if (r1 < NN)
                *(__half2*)&P[(size_t)r1 * 128 + n] =
                    __floats2half2_rn(c[mt][j][2], c[mt][j][3]);
        }
}

// ------------------------- agg width-128 fp16 -> fp16 (unroll x2) ----------
__global__ __launch_bounds__(256) void agg128_kernel(
    const __half* __restrict__ in, __half* __restrict__ out,
    const float* __restrict__ biasExt, int mode)
{
    int node = (blockIdx.x * blockDim.x + threadIdx.x) >> 5;
    if (node >= NN) return;
    int lane = threadIdx.x & 31;
    float di = g_dinv[node];
    uint2 u = *(const uint2*)&in[(size_t)node * 128 + lane * 4];
    float2 t0 = __half22float2(*(__half2*)&u.x);
    float2 t1 = __half22float2(*(__half2*)&u.y);
    float a0 = di * t0.x, a1 = di * t0.y, a2 = di * t1.x, a3 = di * t1.y;
    int s = g_off[node] + g_bpre[node >> 8];
    int e = g_off[node + 1] + g_bpre[(node + 1) >> 8];
    int k = s;
    for (; k + 1 < e; k += 2) {        // 2 independent gather chains (MLP)
        int j0 = g_src[k], j1 = g_src[k + 1];
        float w0 = g_dinv[j0], w1 = g_dinv[j1];
        uint2 r0v = *(const uint2*)&in[(size_t)j0 * 128 + lane * 4];
        uint2 r1v = *(const uint2*)&in[(size_t)j1 * 128 + lane * 4];
        float2 p0 = __half22float2(*(__half2*)&r0v.x);
        float2 p1 = __half22float2(*(__half2*)&r0v.y);
        float2 q0 = __half22float2(*(__half2*)&r1v.x);
        float2 q1 = __half22float2(*(__half2*)&r1v.y);
        a0 += w0 * p0.x + w1 * q0.x;
        a1 += w0 * p0.y + w1 * q0.y;
        a2 += w0 * p1.x + w1 * q1.x;
        a3 += w0 * p1.y + w1 * q1.y;
    }
    if (k < e) {
        int j = g_src[k];
        float w = g_dinv[j];
        uint2 r = *(const uint2*)&in[(size_t)j * 128 + lane * 4];
        float2 r0 = __half22float2(*(__half2*)&r.x);
        float2 r1 = __half22float2(*(__half2*)&r.y);
        a0 += w * r0.x; a1 += w * r0.y; a2 += w * r1.x; a3 += w * r1.y;
    }
    float b0 = 0.f, b1 = 0.f, b2 = 0.f, b3 = 0.f;
    if (mode == 0) {
        b0 = g_bq[lane * 4]; b1 = g_bq[lane * 4 + 1];
        b2 = g_bq[lane * 4 + 2]; b3 = g_bq[lane * 4 + 3];
    } else if (mode == 1) {
        b0 = biasExt[lane * 4]; b1 = biasExt[lane * 4 + 1];
        b2 = biasExt[lane * 4 + 2]; b3 = biasExt[lane * 4 + 3];
    }
    uint2 o;
    *(__half2*)&o.x = __floats2half2_rn(a0 * di + b0, a1 * di + b1);
    *(__half2*)&o.y = __floats2half2_rn(a2 * di + b2, a3 * di + b3);
    *(uint2*)&out[(size_t)node * 128 + lane * 4] = o;
}

// ------------------------- GEMM-MV (HMMA) + fused reparam ------------------
__global__ __launch_bounds__(256) void gemmMV_kernel(
    const __half* __restrict__ G, const float* __restrict__ noise,
    float* __restrict__ O)
{
    __shared__ __align__(16) __half As[128 * 72];
    __shared__ __align__(16) __half Bs[128 * 72];
    int tid = threadIdx.x, lane = tid & 31, wid = tid >> 5;
    int wm = (wid & 3) * 32, wn = (wid >> 2) * 64;
    int rowBase = blockIdx.x * 128;
    float c[2][8][4];
#pragma unroll
    for (int mt = 0; mt < 2; mt++)
#pragma unroll
        for (int j = 0; j < 8; j++)
#pragma unroll
            for (int q = 0; q < 4; q++) c[mt][j][q] = 0.f;

    for (int s = 0; s < 2; s++) {
        int kb = s * 64;
#pragma unroll
        for (int l = 0; l < 4; l++) {
            int hid = tid + l * 256;
            int r = hid >> 3, c8 = hid & 7;
            int gr = rowBase + r;
            uint4 u = make_uint4(0u, 0u, 0u, 0u);
            if (gr < NN) u = *(const uint4*)&G[(size_t)gr * 128 + kb + c8 * 8];
            *(uint4*)&As[r * 72 + c8 * 8] = u;
        }
#pragma unroll
        for (int l = 0; l < 4; l++) {
            int hid = tid + l * 256;
            int n = hid >> 3, c8 = hid & 7;
            *(uint4*)&Bs[n * 72 + c8 * 8] = *(const uint4*)&g_WcatTH[n * 128 + kb + c8 * 8];
        }
        __syncthreads();
#pragma unroll
        for (int kk = 0; kk < 4; kk++) {
            uint32_t a[2][4], b[4][4];
#pragma unroll
            for (int mt = 0; mt < 2; mt++) {
                int row = wm + mt * 16 + (lane & 7) + 8 * ((lane >> 3) & 1);
                int col = kk * 16 + 8 * (lane >> 4);
                ldsm_x4(s2u(&As[row * 72 + col]), a[mt][0], a[mt][1], a[mt][2], a[mt][3]);
            }
#pragma unroll
            for (int jp = 0; jp < 4; jp++) {
                int row = wn + jp * 16 + (lane & 7) + 8 * (lane >> 4);
                int col = kk * 16 + 8 * ((lane >> 3) & 1);
                ldsm_x4(s2u(&Bs[row * 72 + col]), b[jp][0], b[jp][1], b[jp][2], b[jp][3]);
            }
#pragma unroll
            for (int mt = 0; mt < 2; mt++)
#pragma unroll
                for (int jp = 0; jp < 4; jp++) {
                    mma16816(c[mt][jp * 2],     a[mt], b[jp][0], b[jp][1]);
                    mma16816(c[mt][jp * 2 + 1], a[mt], b[jp][2], b[jp][3]);
                }
        }
        __syncthreads();
    }
    // epilogue: c0=mean(r0,L), c1=lv(r0,L); c2/c3 for r0+8; fused reparam.
#pragma unroll
    for (int mt = 0; mt < 2; mt++)
#pragma unroll
        for (int j = 0; j < 8; j++) {
            int nabs = wn + j * 8 + 2 * (lane & 3);
            int L = nabs >> 1;
            float bm_ = g_bcat[nabs], bv_ = g_bcat[nabs + 1];
#pragma unroll
            for (int h = 0; h < 2; h++) {
                int r = rowBase + wm + mt * 16 + (lane >> 2) + h * 8;
                if (r < NN) {
                    float mean = c[mt][j][h * 2]     + bm_;
                    float lv   = c[mt][j][h * 2 + 1] + bv_;
                    size_t o = (size_t)r * 64 + L;
                    float z = noise[o] * expf(0.5f * lv) + mean;
                    O[o] = z;                    // over own (dead) G rows
                    O[3200000 + o] = mean;
                    O[6400000 + o] = lv;
                }
            }
        }
}

// ------------------------- host launcher -----------------------------------
extern "C" void kernel_launch(void* const* d_in, const int* in_sizes, int n_in,
                              void* d_out, int out_size)
{
    const float* feature   = (const float*)d_in[0];
    const float* condition = (const float*)d_in[1];
    const void*  edge_ix   = d_in[2];
    const float* noise     = (const float*)d_in[3];
    const float* W1 = (const float*)d_in[4];
    const float* b1 = (const float*)d_in[5];
    const float* W2 = (const float*)d_in[6];
    const float* b2 = (const float*)d_in[7];
    const float* W3 = (const float*)d_in[8];
    const float* b3 = (const float*)d_in[9];
    const float* Wm = (const float*)d_in[10];
    const float* bm = (const float*)d_in[11];
    const float* Wv = (const float*)d_in[12];
    const float* bv = (const float*)d_in[13];
    float* O = (float*)d_out;

    __half* P = (__half*)O;               // [0 : 3.2M floats) fp16
    __half* Q = (__half*)(O + 3200000);
    __half* R = (__half*)(O + 6400000);
    __half* G = (__half*)O;               // over dead P

    const int TB = 256;
    const int gE  = (NE + TB - 1) / TB;       // 2344
    const int gG  = (NN + 127) / 128;         // 391
    const int gW  = (NN * 32) / TB;           // 6250
    const int gS1 = (65792 + TB - 1) / TB;    // 257

    setup1_kernel<<<gS1, TB>>>((const int*)edge_ix, W1, W2, W3, b1, b2, Wm, Wv, bm, bv);
    count_deg_kernel<<<gE, TB>>>(edge_ix);
    scan1_kernel<<<NB_SCAN, 256>>>();
    scan2_kernel<<<1, 256>>>();
    scatter_kernel<<<gE, TB>>>(edge_ix);

    gemmP_kernel<<<gG, TB>>>(feature, condition, P);

    agg128_kernel<<<gW, TB>>>(P, Q, nullptr, 0);   // Q = A·P + bq
    agg128_kernel<<<gW, TB>>>(Q, R, b3, 1);        // R = A·Q + b3
    agg128_kernel<<<gW, TB>>>(R, G, nullptr, 2);   // G = A·R

    gemmMV_kernel<<<gG, TB>>>(G, noise, O);
}

// round 14
// speedup vs baseline: 1.0745x; 1.0745x over previous
#include <cuda_runtime.h>
#include <cuda_fp16.h>
#include <cstdint>

// ---------------------------------------------------------------------------
// CombinedHiddenEncoder — R14: capture-forked aux stream overlaps the dense
// chain (weight-fold -> gemmP) with the CSR-build chain (zero/count/scan/
// scatter); join before agg1. Compute kernels unchanged from R12/R13.
//
//   chainA (s0): zero+detect -> count_deg -> scan1 -> scan2 -> scatter
//   chainB (aux): fold (UT,bq,WcatTH,bcat) -> P = [F|C]@UT^T (HMMA)
//   join -> Q = A·P + bq -> R = A·Q + b3 -> G = A·R
//        -> (mean|lv) = G@WcatTH^T + bcat, z fused (HMMA)
//
// d_out (O = float[9.6M]): P=[0:3.2M) Q=[3.2M:6.4M) R=[6.4M:9.6M) fp16;
//   G over dead P; z over own G rows; mean over dead Q; lv over dead R.
// ---------------------------------------------------------------------------

#define NN 50000
#define NE 600000
#define NB_SCAN 196

// ------------------------- device statics (~2 MB) --------------------------
__device__ unsigned short g_src[NE];
__device__ int    g_cnt[NN];
__device__ int    g_off[NN + 1];          // partial-exclusive (add g_bpre)
__device__ float  g_dinv[NN];
__device__ int    g_bsum[256];
__device__ int    g_bpre[256];
__device__ __half g_UT[128 * 384];        // [n][k], k<256 from U1, rest U2
__device__ float  g_bq[128];
__device__ __half g_WcatTH[128 * 128];    // [n][k], n interleaved (e=Wm,o=Wv)
__device__ float  g_bcat[128];            // interleaved [bm|bv]
__device__ int    g_is64;

// ------------------------- mma helpers -------------------------------------
__device__ __forceinline__ uint32_t s2u(const void* p) {
    return (uint32_t)__cvta_generic_to_shared(p);
}
__device__ __forceinline__ void ldsm_x4(uint32_t addr, uint32_t& r0, uint32_t& r1,
                                        uint32_t& r2, uint32_t& r3) {
    asm volatile("ldmatrix.sync.aligned.m8n8.x4.shared.b16 {%0,%1,%2,%3}, [%4];"
                 : "=r"(r0), "=r"(r1), "=r"(r2), "=r"(r3) : "r"(addr));
}
__device__ __forceinline__ void mma16816(float* c, const uint32_t* a,
                                         uint32_t b0, uint32_t b1) {
    asm volatile(
        "mma.sync.aligned.m16n8k16.row.col.f32.f16.f16.f32 "
        "{%0,%1,%2,%3}, {%4,%5,%6,%7}, {%8,%9}, {%0,%1,%2,%3};"
        : "+f"(c[0]), "+f"(c[1]), "+f"(c[2]), "+f"(c[3])
        : "r"(a[0]), "r"(a[1]), "r"(a[2]), "r"(a[3]), "r"(b0), "r"(b1));
}

// ------------------------- chain A: CSR build ------------------------------
__global__ void zero_detect_kernel(const int* __restrict__ ei32) {
    int i = blockIdx.x * blockDim.x + threadIdx.x;
    if (i < NN) g_cnt[i] = 0;
    if (blockIdx.x == 0 && threadIdx.x < 32) {   // int64 detect (warp)
        int nz = 0;
        for (int k = 0; k < 16; k++) nz |= ei32[2 * (threadIdx.x * 16 + k) + 1];
        nz = __reduce_or_sync(0xffffffffu, nz);
        if (threadIdx.x == 0) g_is64 = (nz == 0) ? 1 : 0;
    }
}

__device__ __forceinline__ int edge_val(const void* ei, int idx) {
    if (g_is64) return (int)((const long long*)ei)[idx];
    return ((const int*)ei)[idx];
}

__global__ void count_deg_kernel(const void* __restrict__ ei) {
    int e = blockIdx.x * blockDim.x + threadIdx.x;
    if (e >= NE) return;
    atomicAdd(&g_cnt[edge_val(ei, NE + e)], 1);
}

// Partial-exclusive scan per block; also dinv; re-zeroes cnt for scatter.
__global__ void scan1_kernel() {
    __shared__ int s[256];
    int tid = threadIdx.x;
    int i = blockIdx.x * 256 + tid;
    int v = (i < NN) ? g_cnt[i] : 0;
    if (i < NN) { g_dinv[i] = rsqrtf((float)(v + 1)); g_cnt[i] = 0; }
    s[tid] = v;
    __syncthreads();
    for (int off = 1; off < 256; off <<= 1) {
        int t = (tid >= off) ? s[tid - off] : 0;
        __syncthreads();
        s[tid] += t;
        __syncthreads();
    }
    if (i < NN) g_off[i] = s[tid] - v;   // block-local exclusive
    if (tid == 255) g_bsum[blockIdx.x] = s[255];
}

// Block prefix; thread 195 patches g_off[NN] so end(NN-1) resolves to NE.
__global__ void scan2_kernel() {
    __shared__ int s[256];
    int tid = threadIdx.x;
    int v = (tid < NB_SCAN) ? g_bsum[tid] : 0;
    s[tid] = v;
    __syncthreads();
    for (int off = 1; off < 256; off <<= 1) {
        int t = (tid >= off) ? s[tid - off] : 0;
        __syncthreads();
        s[tid] += t;
        __syncthreads();
    }
    int bpre = s[tid] - v;
    g_bpre[tid] = bpre;
    if (tid == (NN >> 8)) g_off[NN] = NE - bpre;   // 50000>>8 = 195
}

__global__ void scatter_kernel(const void* __restrict__ ei) {
    int e = blockIdx.x * blockDim.x + threadIdx.x;
    if (e >= NE) return;
    int s = edge_val(ei, e);
    int d = edge_val(ei, NE + e);
    int p = g_off[d] + g_bpre[d >> 8] + atomicAdd(&g_cnt[d], 1);
    g_src[p] = (unsigned short)s;
}

// ------------------------- chain B: weight folding -------------------------
__global__ void fold_kernel(const float* __restrict__ W1, const float* __restrict__ W2,
                            const float* __restrict__ W3, const float* __restrict__ b1,
                            const float* __restrict__ b2,
                            const float* __restrict__ Wm, const float* __restrict__ Wv,
                            const float* __restrict__ bm, const float* __restrict__ bv) {
    int idx = blockIdx.x * blockDim.x + threadIdx.x;
    if (idx < 49152) {                             // g_UT[n][k]
        int n = idx / 384, k = idx % 384;
        float a = 0.f;
        if (k < 256) {
            for (int j = 0; j < 128; j++) a += W1[k * 128 + j] * W3[j * 128 + n];
        } else {
            int kc = k - 256;
            for (int j = 0; j < 128; j++) a += W2[kc * 128 + j] * W3[(128 + j) * 128 + n];
        }
        g_UT[n * 384 + k] = __float2half_rn(a);
    } else if (idx < 49280) {                      // bq
        int n = idx - 49152;
        float a = 0.f;
        for (int j = 0; j < 128; j++)
            a += b1[j] * W3[j * 128 + n] + b2[j] * W3[(128 + j) * 128 + n];
        g_bq[n] = a;
    } else if (idx < 65664) {                      // g_WcatTH[n][k]
        int t = idx - 49280;
        int n = t >> 7, k = t & 127;
        float v = (n & 1) ? Wv[k * 64 + (n >> 1)] : Wm[k * 64 + (n >> 1)];
        g_WcatTH[n * 128 + k] = __float2half_rn(v);
    } else if (idx < 65792) {                      // bcat interleaved
        int n = idx - 65664;
        g_bcat[n] = (n & 1) ? bv[n >> 1] : bm[n >> 1];
    }
}

// ------------------------- GEMM-P (HMMA): P(fp16) = [F|C]@UT^T -------------
__global__ __launch_bounds__(256) void gemmP_kernel(
    const float* __restrict__ F, const float* __restrict__ C,
    __half* __restrict__ P)
{
    __shared__ __align__(16) __half As[128 * 72];
    __shared__ __align__(16) __half Bs[128 * 72];
    int tid = threadIdx.x, lane = tid & 31, wid = tid >> 5;
    int wm = (wid & 3) * 32, wn = (wid >> 2) * 64;
    int rowBase = blockIdx.x * 128;
    float c[2][8][4];
#pragma unroll
    for (int mt = 0; mt < 2; mt++)
#pragma unroll
        for (int j = 0; j < 8; j++)
#pragma unroll
            for (int q = 0; q < 4; q++) c[mt][j][q] = 0.f;

    for (int s = 0; s < 6; s++) {
        const float* A = (s < 4) ? F : C;
        int ldA = (s < 4) ? 256 : 128;
        int kb  = (s < 4) ? s * 64 : (s - 4) * 64;   // A-local k offset
        int kbB = s * 64;                             // GLOBAL k offset into UT
#pragma unroll
        for (int l = 0; l < 8; l++) {
            int fid = tid + l * 256;
            int r = fid >> 4, c4 = fid & 15;
            int gr = rowBase + r;
            float4 v = make_float4(0.f, 0.f, 0.f, 0.f);
            if (gr < NN) v = *(const float4*)&A[(size_t)gr * ldA + kb + c4 * 4];
            __half2 h0 = __floats2half2_rn(v.x, v.y);
            __half2 h1 = __floats2half2_rn(v.z, v.w);
            uint2 u = make_uint2(*(uint32_t*)&h0, *(uint32_t*)&h1);
            *(uint2*)&As[r * 72 + c4 * 4] = u;
        }
#pragma unroll
        for (int l = 0; l < 4; l++) {
            int hid = tid + l * 256;
            int n = hid >> 3, c8 = hid & 7;
            *(uint4*)&Bs[n * 72 + c8 * 8] = *(const uint4*)&g_UT[n * 384 + kbB + c8 * 8];
        }
        __syncthreads();
#pragma unroll
        for (int kk = 0; kk < 4; kk++) {
            uint32_t a[2][4], b[4][4];
#pragma unroll
            for (int mt = 0; mt < 2; mt++) {
                int row = wm + mt * 16 + (lane & 7) + 8 * ((lane >> 3) & 1);
                int col = kk * 16 + 8 * (lane >> 4);
                ldsm_x4(s2u(&As[row * 72 + col]), a[mt][0], a[mt][1], a[mt][2], a[mt][3]);
            }
#pragma unroll
            for (int jp = 0; jp < 4; jp++) {
                int row = wn + jp * 16 + (lane & 7) + 8 * (lane >> 4);
                int col = kk * 16 + 8 * ((lane >> 3) & 1);
                ldsm_x4(s2u(&Bs[row * 72 + col]), b[jp][0], b[jp][1], b[jp][2], b[jp][3]);
            }
#pragma unroll
            for (int mt = 0; mt < 2; mt++)
#pragma unroll
                for (int jp = 0; jp < 4; jp++) {
                    mma16816(c[mt][jp * 2],     a[mt], b[jp][0], b[jp][1]);
                    mma16816(c[mt][jp * 2 + 1], a[mt], b[jp][2], b[jp][3]);
                }
        }
        __syncthreads();
    }
#pragma unroll
    for (int mt = 0; mt < 2; mt++)
#pragma unroll
        for (int j = 0; j < 8; j++) {
            int r0 = rowBase + wm + mt * 16 + (lane >> 2);
            int n  = wn + j * 8 + 2 * (lane & 3);
            if (r0 < NN)
                *(__half2*)&P[(size_t)r0 * 128 + n] =
                    __floats2half2_rn(c[mt][j][0], c[mt][j][1]);
            int r1 = r0 + 8;
            if (r1 < NN)
                *(__half2*)&P[(size_t)r1 * 128 + n] =
                    __floats2half2_rn(c[mt][j][2], c[mt][j][3]);
        }
}

// ------------------------- agg width-128 fp16 -> fp16 ----------------------
__global__ __launch_bounds__(256) void agg128_kernel(
    const __half* __restrict__ in, __half* __restrict__ out,
    const float* __restrict__ biasExt, int mode)
{
    int node = (blockIdx.x * blockDim.x + threadIdx.x) >> 5;
    if (node >= NN) return;
    int lane = threadIdx.x & 31;
    float di = g_dinv[node];
    uint2 u = *(const uint2*)&in[(size_t)node * 128 + lane * 4];
    float2 t0 = __half22float2(*(__half2*)&u.x);
    float2 t1 = __half22float2(*(__half2*)&u.y);
    float a0 = di * t0.x, a1 = di * t0.y, a2 = di * t1.x, a3 = di * t1.y;
    int s = g_off[node] + g_bpre[node >> 8];
    int e = g_off[node + 1] + g_bpre[(node + 1) >> 8];
    int k = s;
    for (; k + 1 < e; k += 2) {
        int j0 = g_src[k], j1 = g_src[k + 1];
        float w0 = g_dinv[j0], w1 = g_dinv[j1];
        uint2 r0v = *(const uint2*)&in[(size_t)j0 * 128 + lane * 4];
        uint2 r1v = *(const uint2*)&in[(size_t)j1 * 128 + lane * 4];
        float2 p0 = __half22float2(*(__half2*)&r0v.x);
        float2 p1 = __half22float2(*(__half2*)&r0v.y);
        float2 q0 = __half22float2(*(__half2*)&r1v.x);
        float2 q1 = __half22float2(*(__half2*)&r1v.y);
        a0 += w0 * p0.x + w1 * q0.x;
        a1 += w0 * p0.y + w1 * q0.y;
        a2 += w0 * p1.x + w1 * q1.x;
        a3 += w0 * p1.y + w1 * q1.y;
    }
    if (k < e) {
        int j = g_src[k];
        float w = g_dinv[j];
        uint2 r = *(const uint2*)&in[(size_t)j * 128 + lane * 4];
        float2 r0 = __half22float2(*(__half2*)&r.x);
        float2 r1 = __half22float2(*(__half2*)&r.y);
        a0 += w * r0.x; a1 += w * r0.y; a2 += w * r1.x; a3 += w * r1.y;
    }
    float b0 = 0.f, b1 = 0.f, b2 = 0.f, b3 = 0.f;
    if (mode == 0) {
        b0 = g_bq[lane * 4]; b1 = g_bq[lane * 4 + 1];
        b2 = g_bq[lane * 4 + 2]; b3 = g_bq[lane * 4 + 3];
    } else if (mode == 1) {
        b0 = biasExt[lane * 4]; b1 = biasExt[lane * 4 + 1];
        b2 = biasExt[lane * 4 + 2]; b3 = biasExt[lane * 4 + 3];
    }
    uint2 o;
    *(__half2*)&o.x = __floats2half2_rn(a0 * di + b0, a1 * di + b1);
    *(__half2*)&o.y = __floats2half2_rn(a2 * di + b2, a3 * di + b3);
    *(uint2*)&out[(size_t)node * 128 + lane * 4] = o;
}

// ------------------------- GEMM-MV (HMMA) + fused reparam ------------------
__global__ __launch_bounds__(256) void gemmMV_kernel(
    const __half* __restrict__ G, const float* __restrict__ noise,
    float* __restrict__ O)
{
    __shared__ __align__(16) __half As[128 * 72];
    __shared__ __align__(16) __half Bs[128 * 72];
    int tid = threadIdx.x, lane = tid & 31, wid = tid >> 5;
    int wm = (wid & 3) * 32, wn = (wid >> 2) * 64;
    int rowBase = blockIdx.x * 128;
    float c[2][8][4];
#pragma unroll
    for (int mt = 0; mt < 2; mt++)
#pragma unroll
        for (int j = 0; j < 8; j++)
#pragma unroll
            for (int q = 0; q < 4; q++) c[mt][j][q] = 0.f;

    for (int s = 0; s < 2; s++) {
        int kb = s * 64;
#pragma unroll
        for (int l = 0; l < 4; l++) {
            int hid = tid + l * 256;
            int r = hid >> 3, c8 = hid & 7;
            int gr = rowBase + r;
            uint4 u = make_uint4(0u, 0u, 0u, 0u);
            if (gr < NN) u = *(const uint4*)&G[(size_t)gr * 128 + kb + c8 * 8];
            *(uint4*)&As[r * 72 + c8 * 8] = u;
        }
#pragma unroll
        for (int l = 0; l < 4; l++) {
            int hid = tid + l * 256;
            int n = hid >> 3, c8 = hid & 7;
            *(uint4*)&Bs[n * 72 + c8 * 8] = *(const uint4*)&g_WcatTH[n * 128 + kb + c8 * 8];
        }
        __syncthreads();
#pragma unroll
        for (int kk = 0; kk < 4; kk++) {
            uint32_t a[2][4], b[4][4];
#pragma unroll
            for (int mt = 0; mt < 2; mt++) {
                int row = wm + mt * 16 + (lane & 7) + 8 * ((lane >> 3) & 1);
                int col = kk * 16 + 8 * (lane >> 4);
                ldsm_x4(s2u(&As[row * 72 + col]), a[mt][0], a[mt][1], a[mt][2], a[mt][3]);
            }
#pragma unroll
            for (int jp = 0; jp < 4; jp++) {
                int row = wn + jp * 16 + (lane & 7) + 8 * (lane >> 4);
                int col = kk * 16 + 8 * ((lane >> 3) & 1);
                ldsm_x4(s2u(&Bs[row * 72 + col]), b[jp][0], b[jp][1], b[jp][2], b[jp][3]);
            }
#pragma unroll
            for (int mt = 0; mt < 2; mt++)
#pragma unroll
                for (int jp = 0; jp < 4; jp++) {
                    mma16816(c[mt][jp * 2],     a[mt], b[jp][0], b[jp][1]);
                    mma16816(c[mt][jp * 2 + 1], a[mt], b[jp][2], b[jp][3]);
                }
        }
        __syncthreads();
    }
#pragma unroll
    for (int mt = 0; mt < 2; mt++)
#pragma unroll
        for (int j = 0; j < 8; j++) {
            int nabs = wn + j * 8 + 2 * (lane & 3);
            int L = nabs >> 1;
            float bm_ = g_bcat[nabs], bv_ = g_bcat[nabs + 1];
#pragma unroll
            for (int h = 0; h < 2; h++) {
                int r = rowBase + wm + mt * 16 + (lane >> 2) + h * 8;
                if (r < NN) {
                    float mean = c[mt][j][h * 2]     + bm_;
                    float lv   = c[mt][j][h * 2 + 1] + bv_;
                    size_t o = (size_t)r * 64 + L;
                    float z = noise[o] * expf(0.5f * lv) + mean;
                    O[o] = z;                    // over own (dead) G rows
                    O[3200000 + o] = mean;
                    O[6400000 + o] = lv;
                }
            }
        }
}

// ------------------------- host launcher -----------------------------------
extern "C" void kernel_launch(void* const* d_in, const int* in_sizes, int n_in,
                              void* d_out, int out_size)
{
    const float* feature   = (const float*)d_in[0];
    const float* condition = (const float*)d_in[1];
    const void*  edge_ix   = d_in[2];
    const float* noise     = (const float*)d_in[3];
    const float* W1 = (const float*)d_in[4];
    const float* b1 = (const float*)d_in[5];
    const float* W2 = (const float*)d_in[6];
    const float* b2 = (const float*)d_in[7];
    const float* W3 = (const float*)d_in[8];
    const float* b3 = (const float*)d_in[9];
    const float* Wm = (const float*)d_in[10];
    const float* bm = (const float*)d_in[11];
    const float* Wv = (const float*)d_in[12];
    const float* bv = (const float*)d_in[13];
    float* O = (float*)d_out;

    __half* P = (__half*)O;               // [0 : 3.2M floats) fp16
    __half* Q = (__half*)(O + 3200000);
    __half* R = (__half*)(O + 6400000);
    __half* G = (__half*)O;               // over dead P

    const int TB = 256;
    const int gN  = (NN + TB - 1) / TB;       // 196
    const int gE  = (NE + TB - 1) / TB;       // 2344
    const int gG  = (NN + 127) / 128;         // 391
    const int gW  = (NN * 32) / TB;           // 6250
    const int gFold = (65792 + TB - 1) / TB;  // 257

    // one-time aux stream + fork/join events (created on the uncaptured
    // correctness call; reused verbatim inside the captured graph)
    static cudaStream_t s_aux = nullptr;
    static cudaEvent_t ev_fork = nullptr, ev_join = nullptr;
    if (s_aux == nullptr) {
        cudaStreamCreateWithFlags(&s_aux, cudaStreamNonBlocking);
        cudaEventCreateWithFlags(&ev_fork, cudaEventDisableTiming);
        cudaEventCreateWithFlags(&ev_join, cudaEventDisableTiming);
    }

    // fork: chain B (dense) on aux stream
    cudaEventRecord(ev_fork, 0);
    cudaStreamWaitEvent(s_aux, ev_fork, 0);
    fold_kernel<<<gFold, TB, 0, s_aux>>>(W1, W2, W3, b1, b2, Wm, Wv, bm, bv);
    gemmP_kernel<<<gG, TB, 0, s_aux>>>(feature, condition, P);
    cudaEventRecord(ev_join, s_aux);

    // chain A (CSR build) on the main stream
    zero_detect_kernel<<<gN, TB>>>((const int*)edge_ix);
    count_deg_kernel<<<gE, TB>>>(edge_ix);
    scan1_kernel<<<NB_SCAN, 256>>>();
    scan2_kernel<<<1, 256>>>();
    scatter_kernel<<<gE, TB>>>(edge_ix);

    // join, then the serial tail
    cudaStreamWaitEvent(0, ev_join, 0);
    agg128_kernel<<<gW, TB>>>(P, Q, nullptr, 0);   // Q = A·P + bq
    agg128_kernel<<<gW, TB>>>(Q, R, b3, 1);        // R = A·Q + b3
    agg128_kernel<<<gW, TB>>>(R, G, nullptr, 2);   // G = A·R
    gemmMV_kernel<<<gG, TB>>>(G, noise, O);
}

// round 15
// speedup vs baseline: 1.0896x; 1.0140x over previous
#include <cuda_runtime.h>
#include <cuda_fp16.h>
#include <cstdint>

// ---------------------------------------------------------------------------
// CombinedHiddenEncoder — R15: agg rework (half-warp per gathered row; one
// 512B warp-load covers 2 edges) + zero-pass elimination (g_cnt re-zeroed by
// gemmMV for the next invocation; statics are zero-init on first call).
//
//   chainA (s0): detect -> count_deg -> scan1 -> scan2 -> scatter
//   chainB (aux): fold -> P = [F|C]@UT^T (HMMA)
//   join -> Q = A·P + bq -> R = A·Q + b3 -> G = A·R
//        -> (mean|lv) = G@WcatTH^T + bcat, z fused (HMMA; also re-zeros cnt)
//
// d_out (O = float[9.6M]): P=[0:3.2M) Q=[3.2M:6.4M) R=[6.4M:9.6M) fp16;
//   G over dead P; z over own G rows; mean over dead Q; lv over dead R.
// ---------------------------------------------------------------------------

#define NN 50000
#define NE 600000
#define NB_SCAN 196

// ------------------------- device statics (~2 MB) --------------------------
__device__ unsigned short g_src[NE];
__device__ int    g_cnt[NN];              // ZERO at entry (init/gemmMV invariant)
__device__ int    g_off[NN + 1];          // partial-exclusive (add g_bpre)
__device__ float  g_dinv[NN];
__device__ int    g_bsum[256];
__device__ int    g_bpre[256];
__device__ __half g_UT[128 * 384];        // [n][k], k<256 from U1, rest U2
__device__ float  g_bq[128];
__device__ __half g_WcatTH[128 * 128];    // [n][k], n interleaved (e=Wm,o=Wv)
__device__ float  g_bcat[128];            // interleaved [bm|bv]
__device__ int    g_is64;

// ------------------------- mma helpers -------------------------------------
__device__ __forceinline__ uint32_t s2u(const void* p) {
    return (uint32_t)__cvta_generic_to_shared(p);
}
__device__ __forceinline__ void ldsm_x4(uint32_t addr, uint32_t& r0, uint32_t& r1,
                                        uint32_t& r2, uint32_t& r3) {
    asm volatile("ldmatrix.sync.aligned.m8n8.x4.shared.b16 {%0,%1,%2,%3}, [%4];"
                 : "=r"(r0), "=r"(r1), "=r"(r2), "=r"(r3) : "r"(addr));
}
__device__ __forceinline__ void mma16816(float* c, const uint32_t* a,
                                         uint32_t b0, uint32_t b1) {
    asm volatile(
        "mma.sync.aligned.m16n8k16.row.col.f32.f16.f16.f32 "
        "{%0,%1,%2,%3}, {%4,%5,%6,%7}, {%8,%9}, {%0,%1,%2,%3};"
        : "+f"(c[0]), "+f"(c[1]), "+f"(c[2]), "+f"(c[3])
        : "r"(a[0]), "r"(a[1]), "r"(a[2]), "r"(a[3]), "r"(b0), "r"(b1));
}

// ------------------------- chain A: CSR build ------------------------------
__global__ void detect_kernel(const int* __restrict__ ei32) {
    if (threadIdx.x < 32) {
        int nz = 0;
        for (int k = 0; k < 16; k++) nz |= ei32[2 * (threadIdx.x * 16 + k) + 1];
        nz = __reduce_or_sync(0xffffffffu, nz);
        if (threadIdx.x == 0) g_is64 = (nz == 0) ? 1 : 0;
    }
}

__device__ __forceinline__ int edge_val(const void* ei, int idx) {
    if (g_is64) return (int)((const long long*)ei)[idx];
    return ((const int*)ei)[idx];
}

__global__ void count_deg_kernel(const void* __restrict__ ei) {
    int e = blockIdx.x * blockDim.x + threadIdx.x;
    if (e >= NE) return;
    atomicAdd(&g_cnt[edge_val(ei, NE + e)], 1);
}

// Partial-exclusive scan per block; also dinv; re-zeroes cnt for scatter.
__global__ void scan1_kernel() {
    __shared__ int s[256];
    int tid = threadIdx.x;
    int i = blockIdx.x * 256 + tid;
    int v = (i < NN) ? g_cnt[i] : 0;
    if (i < NN) { g_dinv[i] = rsqrtf((float)(v + 1)); g_cnt[i] = 0; }
    s[tid] = v;
    __syncthreads();
    for (int off = 1; off < 256; off <<= 1) {
        int t = (tid >= off) ? s[tid - off] : 0;
        __syncthreads();
        s[tid] += t;
        __syncthreads();
    }
    if (i < NN) g_off[i] = s[tid] - v;   // block-local exclusive
    if (tid == 255) g_bsum[blockIdx.x] = s[255];
}

// Block prefix; thread 195 patches g_off[NN] so end(NN-1) resolves to NE.
__global__ void scan2_kernel() {
    __shared__ int s[256];
    int tid = threadIdx.x;
    int v = (tid < NB_SCAN) ? g_bsum[tid] : 0;
    s[tid] = v;
    __syncthreads();
    for (int off = 1; off < 256; off <<= 1) {
        int t = (tid >= off) ? s[tid - off] : 0;
        __syncthreads();
        s[tid] += t;
        __syncthreads();
    }
    int bpre = s[tid] - v;
    g_bpre[tid] = bpre;
    if (tid == (NN >> 8)) g_off[NN] = NE - bpre;   // 50000>>8 = 195
}

__global__ void scatter_kernel(const void* __restrict__ ei) {
    int e = blockIdx.x * blockDim.x + threadIdx.x;
    if (e >= NE) return;
    int s = edge_val(ei, e);
    int d = edge_val(ei, NE + e);
    int p = g_off[d] + g_bpre[d >> 8] + atomicAdd(&g_cnt[d], 1);
    g_src[p] = (unsigned short)s;
}

// ------------------------- chain B: weight folding -------------------------
__global__ void fold_kernel(const float* __restrict__ W1, const float* __restrict__ W2,
                            const float* __restrict__ W3, const float* __restrict__ b1,
                            const float* __restrict__ b2,
                            const float* __restrict__ Wm, const float* __restrict__ Wv,
                            const float* __restrict__ bm, const float* __restrict__ bv) {
    int idx = blockIdx.x * blockDim.x + threadIdx.x;
    if (idx < 49152) {                             // g_UT[n][k]
        int n = idx / 384, k = idx % 384;
        float a = 0.f;
        if (k < 256) {
            for (int j = 0; j < 128; j++) a += W1[k * 128 + j] * W3[j * 128 + n];
        } else {
            int kc = k - 256;
            for (int j = 0; j < 128; j++) a += W2[kc * 128 + j] * W3[(128 + j) * 128 + n];
        }
        g_UT[n * 384 + k] = __float2half_rn(a);
    } else if (idx < 49280) {                      // bq
        int n = idx - 49152;
        float a = 0.f;
        for (int j = 0; j < 128; j++)
            a += b1[j] * W3[j * 128 + n] + b2[j] * W3[(128 + j) * 128 + n];
        g_bq[n] = a;
    } else if (idx < 65664) {                      // g_WcatTH[n][k]
        int t = idx - 49280;
        int n = t >> 7, k = t & 127;
        float v = (n & 1) ? Wv[k * 64 + (n >> 1)] : Wm[k * 64 + (n >> 1)];
        g_WcatTH[n * 128 + k] = __float2half_rn(v);
    } else if (idx < 65792) {                      // bcat interleaved
        int n = idx - 65664;
        g_bcat[n] = (n & 1) ? bv[n >> 1] : bm[n >> 1];
    }
}

// ------------------------- GEMM-P (HMMA): P(fp16) = [F|C]@UT^T -------------
__global__ __launch_bounds__(256) void gemmP_kernel(
    const float* __restrict__ F, const float* __restrict__ C,
    __half* __restrict__ P)
{
    __shared__ __align__(16) __half As[128 * 72];
    __shared__ __align__(16) __half Bs[128 * 72];
    int tid = threadIdx.x, lane = tid & 31, wid = tid >> 5;
    int wm = (wid & 3) * 32, wn = (wid >> 2) * 64;
    int rowBase = blockIdx.x * 128;
    float c[2][8][4];
#pragma unroll
    for (int mt = 0; mt < 2; mt++)
#pragma unroll
        for (int j = 0; j < 8; j++)
#pragma unroll
            for (int q = 0; q < 4; q++) c[mt][j][q] = 0.f;

    for (int s = 0; s < 6; s++) {
        const float* A = (s < 4) ? F : C;
        int ldA = (s < 4) ? 256 : 128;
        int kb  = (s < 4) ? s * 64 : (s - 4) * 64;   // A-local k offset
        int kbB = s * 64;                             // GLOBAL k offset into UT
#pragma unroll
        for (int l = 0; l < 8; l++) {
            int fid = tid + l * 256;
            int r = fid >> 4, c4 = fid & 15;
            int gr = rowBase + r;
            float4 v = make_float4(0.f, 0.f, 0.f, 0.f);
            if (gr < NN) v = *(const float4*)&A[(size_t)gr * ldA + kb + c4 * 4];
            __half2 h0 = __floats2half2_rn(v.x, v.y);
            __half2 h1 = __floats2half2_rn(v.z, v.w);
            uint2 u = make_uint2(*(uint32_t*)&h0, *(uint32_t*)&h1);
            *(uint2*)&As[r * 72 + c4 * 4] = u;
        }
#pragma unroll
        for (int l = 0; l < 4; l++) {
            int hid = tid + l * 256;
            int n = hid >> 3, c8 = hid & 7;
            *(uint4*)&Bs[n * 72 + c8 * 8] = *(const uint4*)&g_UT[n * 384 + kbB + c8 * 8];
        }
        __syncthreads();
#pragma unroll
        for (int kk = 0; kk < 4; kk++) {
            uint32_t a[2][4], b[4][4];
#pragma unroll
            for (int mt = 0; mt < 2; mt++) {
                int row = wm + mt * 16 + (lane & 7) + 8 * ((lane >> 3) & 1);
                int col = kk * 16 + 8 * (lane >> 4);
                ldsm_x4(s2u(&As[row * 72 + col]), a[mt][0], a[mt][1], a[mt][2], a[mt][3]);
            }
#pragma unroll
            for (int jp = 0; jp < 4; jp++) {
                int row = wn + jp * 16 + (lane & 7) + 8 * (lane >> 4);
                int col = kk * 16 + 8 * ((lane >> 3) & 1);
                ldsm_x4(s2u(&Bs[row * 72 + col]), b[jp][0], b[jp][1], b[jp][2], b[jp][3]);
            }
#pragma unroll
            for (int mt = 0; mt < 2; mt++)
#pragma unroll
                for (int jp = 0; jp < 4; jp++) {
                    mma16816(c[mt][jp * 2],     a[mt], b[jp][0], b[jp][1]);
                    mma16816(c[mt][jp * 2 + 1], a[mt], b[jp][2], b[jp][3]);
                }
        }
        __syncthreads();
    }
#pragma unroll
    for (int mt = 0; mt < 2; mt++)
#pragma unroll
        for (int j = 0; j < 8; j++) {
            int r0 = rowBase + wm + mt * 16 + (lane >> 2);
            int n  = wn + j * 8 + 2 * (lane & 3);
            if (r0 < NN)
                *(__half2*)&P[(size_t)r0 * 128 + n] =
                    __floats2half2_rn(c[mt][j][0], c[mt][j][1]);
            int r1 = r0 + 8;
            if (r1 < NN)
                *(__half2*)&P[(size_t)r1 * 128 + n] =
                    __floats2half2_rn(c[mt][j][2], c[mt][j][3]);
        }
}

// ------------------------- agg: half-warp per row, 2 edges/iter ------------
// Lanes 0-15 handle even edges, 16-31 odd edges; each lane loads 16B (8
// halves) of a gathered row => one 512B warp-load per 2 edges. Halves are
// combined via shfl_xor(16); half 0 stores the fp16 result.
__global__ __launch_bounds__(256) void agg128_kernel(
    const __half* __restrict__ in, __half* __restrict__ out,
    const float* __restrict__ biasExt, int mode)
{
    int node = (blockIdx.x * blockDim.x + threadIdx.x) >> 5;
    if (node >= NN) return;
    int lane = threadIdx.x & 31;
    int half = lane >> 4, hl = lane & 15;
    float di = g_dinv[node];
    float acc[8];
    {   // self term (half 0 only; half 1 starts at zero)
        uint4 u = *(const uint4*)&in[(size_t)node * 128 + hl * 8];
        const __half2* h = (const __half2*)&u;
#pragma unroll
        for (int q = 0; q < 4; q++) {
            float2 f = __half22float2(h[q]);
            acc[2 * q]     = half ? 0.f : di * f.x;
            acc[2 * q + 1] = half ? 0.f : di * f.y;
        }
    }
    int s = g_off[node] + g_bpre[node >> 8];
    int e = g_off[node + 1] + g_bpre[(node + 1) >> 8];
    for (int k = s + half; k < e; k += 2) {
        int j = g_src[k];
        float w = g_dinv[j];
        uint4 r = *(const uint4*)&in[(size_t)j * 128 + hl * 8];
        const __half2* rh = (const __half2*)&r;
#pragma unroll
        for (int q = 0; q < 4; q++) {
            float2 f = __half22float2(rh[q]);
            acc[2 * q]     += w * f.x;
            acc[2 * q + 1] += w * f.y;
        }
    }
#pragma unroll
    for (int i = 0; i < 8; i++)
        acc[i] += __shfl_xor_sync(0xffffffffu, acc[i], 16);
    if (half == 0) {
        const float* brow = (mode == 0) ? g_bq : biasExt;
        __half2 o[4];
#pragma unroll
        for (int q = 0; q < 4; q++) {
            float b0 = (mode == 2) ? 0.f : brow[hl * 8 + 2 * q];
            float b1 = (mode == 2) ? 0.f : brow[hl * 8 + 2 * q + 1];
            o[q] = __floats2half2_rn(acc[2 * q] * di + b0,
                                     acc[2 * q + 1] * di + b1);
        }
        *(uint4*)&out[(size_t)node * 128 + hl * 8] = *(uint4*)o;
    }
}

// ------------------------- GEMM-MV (HMMA) + fused reparam ------------------
// Also re-zeroes g_cnt for the NEXT invocation (blocks 0..195).
__global__ __launch_bounds__(256) void gemmMV_kernel(
    const __half* __restrict__ G, const float* __restrict__ noise,
    float* __restrict__ O)
{
    // next-run counter reset (parallel with this block's own work)
    if (blockIdx.x < NB_SCAN) {
        int zi = blockIdx.x * 256 + threadIdx.x;
        if (zi < NN) g_cnt[zi] = 0;
    }
    __shared__ __align__(16) __half As[128 * 72];
    __shared__ __align__(16) __half Bs[128 * 72];
    int tid = threadIdx.x, lane = tid & 31, wid = tid >> 5;
    int wm = (wid & 3) * 32, wn = (wid >> 2) * 64;
    int rowBase = blockIdx.x * 128;
    float c[2][8][4];
#pragma unroll
    for (int mt = 0; mt < 2; mt++)
#pragma unroll
        for (int j = 0; j < 8; j++)
#pragma unroll
            for (int q = 0; q < 4; q++) c[mt][j][q] = 0.f;

    for (int s = 0; s < 2; s++) {
        int kb = s * 64;
#pragma unroll
        for (int l = 0; l < 4; l++) {
            int hid = tid + l * 256;
            int r = hid >> 3, c8 = hid & 7;
            int gr = rowBase + r;
            uint4 u = make_uint4(0u, 0u, 0u, 0u);
            if (gr < NN) u = *(const uint4*)&G[(size_t)gr * 128 + kb + c8 * 8];
            *(uint4*)&As[r * 72 + c8 * 8] = u;
        }
#pragma unroll
        for (int l = 0; l < 4; l++) {
            int hid = tid + l * 256;
            int n = hid >> 3, c8 = hid & 7;
            *(uint4*)&Bs[n * 72 + c8 * 8] = *(const uint4*)&g_WcatTH[n * 128 + kb + c8 * 8];
        }
        __syncthreads();
#pragma unroll
        for (int kk = 0; kk < 4; kk++) {
            uint32_t a[2][4], b[4][4];
#pragma unroll
            for (int mt = 0; mt < 2; mt++) {
                int row = wm + mt * 16 + (lane & 7) + 8 * ((lane >> 3) & 1);
                int col = kk * 16 + 8 * (lane >> 4);
                ldsm_x4(s2u(&As[row * 72 + col]), a[mt][0], a[mt][1], a[mt][2], a[mt][3]);
            }
#pragma unroll
            for (int jp = 0; jp < 4; jp++) {
                int row = wn + jp * 16 + (lane & 7) + 8 * (lane >> 4);
                int col = kk * 16 + 8 * ((lane >> 3) & 1);
                ldsm_x4(s2u(&Bs[row * 72 + col]), b[jp][0], b[jp][1], b[jp][2], b[jp][3]);
            }
#pragma unroll
            for (int mt = 0; mt < 2; mt++)
#pragma unroll
                for (int jp = 0; jp < 4; jp++) {
                    mma16816(c[mt][jp * 2],     a[mt], b[jp][0], b[jp][1]);
                    mma16816(c[mt][jp * 2 + 1], a[mt], b[jp][2], b[jp][3]);
                }
        }
        __syncthreads();
    }
#pragma unroll
    for (int mt = 0; mt < 2; mt++)
#pragma unroll
        for (int j = 0; j < 8; j++) {
            int nabs = wn + j * 8 + 2 * (lane & 3);
            int L = nabs >> 1;
            float bm_ = g_bcat[nabs], bv_ = g_bcat[nabs + 1];
#pragma unroll
            for (int h = 0; h < 2; h++) {
                int r = rowBase + wm + mt * 16 + (lane >> 2) + h * 8;
                if (r < NN) {
                    float mean = c[mt][j][h * 2]     + bm_;
                    float lv   = c[mt][j][h * 2 + 1] + bv_;
                    size_t o = (size_t)r * 64 + L;
                    float z = noise[o] * expf(0.5f * lv) + mean;
                    O[o] = z;                    // over own (dead) G rows
                    O[3200000 + o] = mean;
                    O[6400000 + o] = lv;
                }
            }
        }
}

// ------------------------- host launcher -----------------------------------
extern "C" void kernel_launch(void* const* d_in, const int* in_sizes, int n_in,
                              void* d_out, int out_size)
{
    const float* feature   = (const float*)d_in[0];
    const float* condition = (const float*)d_in[1];
    const void*  edge_ix   = d_in[2];
    const float* noise     = (const float*)d_in[3];
    const float* W1 = (const float*)d_in[4];
    const float* b1 = (const float*)d_in[5];
    const float* W2 = (const float*)d_in[6];
    const float* b2 = (const float*)d_in[7];
    const float* W3 = (const float*)d_in[8];
    const float* b3 = (const float*)d_in[9];
    const float* Wm = (const float*)d_in[10];
    const float* bm = (const float*)d_in[11];
    const float* Wv = (const float*)d_in[12];
    const float* bv = (const float*)d_in[13];
    float* O = (float*)d_out;

    __half* P = (__half*)O;               // [0 : 3.2M floats) fp16
    __half* Q = (__half*)(O + 3200000);
    __half* R = (__half*)(O + 6400000);
    __half* G = (__half*)O;               // over dead P

    const int TB = 256;
    const int gE  = (NE + TB - 1) / TB;       // 2344
    const int gG  = (NN + 127) / 128;         // 391
    const int gW  = (NN * 32) / TB;           // 6250
    const int gFold = (65792 + TB - 1) / TB;  // 257

    static cudaStream_t s_aux = nullptr;
    static cudaEvent_t ev_fork = nullptr, ev_join = nullptr;
    if (s_aux == nullptr) {
        cudaStreamCreateWithFlags(&s_aux, cudaStreamNonBlocking);
        cudaEventCreateWithFlags(&ev_fork, cudaEventDisableTiming);
        cudaEventCreateWithFlags(&ev_join, cudaEventDisableTiming);
    }

    // fork: chain B (dense) on aux stream
    cudaEventRecord(ev_fork, 0);
    cudaStreamWaitEvent(s_aux, ev_fork, 0);
    fold_kernel<<<gFold, TB, 0, s_aux>>>(W1, W2, W3, b1, b2, Wm, Wv, bm, bv);
    gemmP_kernel<<<gG, TB, 0, s_aux>>>(feature, condition, P);
    cudaEventRecord(ev_join, s_aux);

    // chain A (CSR build) on the main stream (g_cnt pre-zeroed invariant)
    detect_kernel<<<1, 32>>>((const int*)edge_ix);
    count_deg_kernel<<<gE, TB>>>(edge_ix);
    scan1_kernel<<<NB_SCAN, 256>>>();
    scan2_kernel<<<1, 256>>>();
    scatter_kernel<<<gE, TB>>>(edge_ix);

    // join, then the serial tail
    cudaStreamWaitEvent(0, ev_join, 0);
    agg128_kernel<<<gW, TB>>>(P, Q, nullptr, 0);   // Q = A·P + bq
    agg128_kernel<<<gW, TB>>>(Q, R, b3, 1);        // R = A·Q + b3
    agg128_kernel<<<gW, TB>>>(R, G, nullptr, 2);   // G = A·R
    gemmMV_kernel<<<gG, TB>>>(G, noise, O);        // + re-zero g_cnt
}